// round 1
// baseline (speedup 1.0000x reference)
#include <cuda_runtime.h>
#include <math.h>

#define NN 50000
#define EE 600000
#define CC 128
#define KK 128

// Scratch (static device globals; no runtime allocation allowed)
__device__ float g_out[(size_t)NN * CC];       // softplus(h@W0+b0)
__device__ float g_P[(size_t)NN * 512];        // [pi_f | pi_s | pj_f | pj_s] per node
__device__ float g_e[EE];                      // softplus(edge_attr@Wsh+bsh)
__device__ float g_aggr[(size_t)NN * CC];      // segment-sum accumulator
__device__ float g_stats[2 * CC];              // per-channel sum, sumsq
__device__ float g_Wcat[KK * 512];             // packed [Wf_i|Ws_i|Wf_j|Ws_j]

__device__ __forceinline__ float sp_f(float x) {
    return x > 20.0f ? x : log1pf(__expf(x));
}
__device__ __forceinline__ float sigm_f(float x) {
    return 1.0f / (1.0f + __expf(-x));
}

__global__ void zero_kernel() {
    size_t i = (size_t)blockIdx.x * blockDim.x + threadIdx.x;
    size_t tot = (size_t)NN * CC;
    size_t stride = (size_t)gridDim.x * blockDim.x;
    for (; i < tot; i += stride) g_aggr[i] = 0.0f;
    if (blockIdx.x == 0 && threadIdx.x < 2 * CC) g_stats[threadIdx.x] = 0.0f;
}

// Build Wcat[128][512]: cols 0-127 = Wf[:128] (x_i), 128-255 = Ws[:128],
// 256-383 = Wf[128:256] (x_j), 384-511 = Ws[128:256]
__global__ void prep_wcat(const float* __restrict__ Wf, const float* __restrict__ Ws) {
    int idx = blockIdx.x * blockDim.x + threadIdx.x;
    if (idx >= KK * 512) return;
    int k = idx >> 9;
    int c = idx & 511;
    float v;
    if (c < 128)      v = Wf[k * 128 + c];
    else if (c < 256) v = Ws[k * 128 + (c - 128)];
    else if (c < 384) v = Wf[(128 + k) * 128 + (c - 256)];
    else              v = Ws[(128 + k) * 128 + (c - 384)];
    g_Wcat[idx] = v;
}

// fp32 GEMM: C[M,Nc] = act(A[M,128] @ B[128,Nc] + bias)
// 64x64 tile, 256 threads, 4x4 microtile. K staged in 2 chunks of 64.
template <int ACT>
__global__ void gemm64(const float* __restrict__ A, const float* __restrict__ B,
                       const float* __restrict__ bias, float* __restrict__ Co,
                       int M, int Nc) {
    __shared__ float As[64][68];
    __shared__ float Bs[64][68];
    int tid = threadIdx.x;
    int tx = tid & 15, ty = tid >> 4;
    int row0 = blockIdx.x * 64, col0 = blockIdx.y * 64;
    float acc[4][4] = {};

    for (int kc = 0; kc < KK; kc += 64) {
#pragma unroll
        for (int l = 0; l < 4; l++) {
            int idx4 = tid + l * 256;           // 0..1023 float4 slots
            int m = idx4 >> 4;                  // tile row
            int k4 = (idx4 & 15) << 2;          // tile col (float4 aligned)
            float4 av = make_float4(0.f, 0.f, 0.f, 0.f);
            int gr = row0 + m;
            if (gr < M) av = *(const float4*)(A + (size_t)gr * KK + kc + k4);
            *(float4*)&As[m][k4] = av;
            float4 bv = *(const float4*)(B + (size_t)(kc + m) * Nc + col0 + k4);
            *(float4*)&Bs[m][k4] = bv;
        }
        __syncthreads();
#pragma unroll 16
        for (int k = 0; k < 64; k++) {
            float4 b4 = *(float4*)&Bs[k][tx << 2];
            float a0 = As[ty * 4 + 0][k];
            float a1 = As[ty * 4 + 1][k];
            float a2 = As[ty * 4 + 2][k];
            float a3 = As[ty * 4 + 3][k];
            acc[0][0] += a0 * b4.x; acc[0][1] += a0 * b4.y; acc[0][2] += a0 * b4.z; acc[0][3] += a0 * b4.w;
            acc[1][0] += a1 * b4.x; acc[1][1] += a1 * b4.y; acc[1][2] += a1 * b4.z; acc[1][3] += a1 * b4.w;
            acc[2][0] += a2 * b4.x; acc[2][1] += a2 * b4.y; acc[2][2] += a2 * b4.z; acc[2][3] += a2 * b4.w;
            acc[3][0] += a3 * b4.x; acc[3][1] += a3 * b4.y; acc[3][2] += a3 * b4.z; acc[3][3] += a3 * b4.w;
        }
        __syncthreads();
    }

#pragma unroll
    for (int i = 0; i < 4; i++) {
        int gr = row0 + ty * 4 + i;
        if (gr >= M) continue;
        int gc = col0 + (tx << 2);
        float4 v;
        v.x = acc[i][0]; v.y = acc[i][1]; v.z = acc[i][2]; v.w = acc[i][3];
        if (ACT) {
            v.x = sp_f(v.x + bias[gc + 0]);
            v.y = sp_f(v.y + bias[gc + 1]);
            v.z = sp_f(v.z + bias[gc + 2]);
            v.w = sp_f(v.w + bias[gc + 3]);
        }
        *(float4*)(Co + (size_t)gr * Nc + gc) = v;
    }
}

// e = softplus(edge_attr @ Wsh + bsh): one warp per edge
__global__ void edge_gauss(const float* __restrict__ ea, const float* __restrict__ Wsh,
                           const float* __restrict__ bsh) {
    int t = blockIdx.x * blockDim.x + threadIdx.x;
    int e = t >> 5;
    if (e >= EE) return;
    int lane = t & 31;
    float4 a = *(const float4*)(ea + (size_t)e * 128 + lane * 4);
    float4 w = *(const float4*)(Wsh + lane * 4);
    float d = a.x * w.x + a.y * w.y + a.z * w.z + a.w * w.w;
#pragma unroll
    for (int o = 16; o; o >>= 1) d += __shfl_xor_sync(0xFFFFFFFFu, d, o);
    if (lane == 0) g_e[e] = sp_f(d + bsh[0]);
}

// One warp per edge: gate*core message, vectorized reduction into g_aggr[dst]
__global__ void edge_msg(const int* __restrict__ ei, const float* __restrict__ Wf,
                         const float* __restrict__ Ws, const float* __restrict__ bf,
                         const float* __restrict__ bs) {
    int t = blockIdx.x * blockDim.x + threadIdx.x;
    int e = t >> 5;
    if (e >= EE) return;
    int lane = t & 31;
    int src = __ldg(ei + e);
    int dst = __ldg(ei + EE + e);
    float ev = __ldg(g_e + e);
    int c = lane * 4;

    const float4* Pd = (const float4*)(g_P + (size_t)dst * 512);        // [pi_f|pi_s]
    const float4* Psrc = (const float4*)(g_P + (size_t)src * 512 + 256); // [pj_f|pj_s]
    float4 pif = Pd[lane];
    float4 pis = Pd[32 + lane];
    float4 pjf = Psrc[lane];
    float4 pjs = Psrc[32 + lane];

    float4 wfe = *(const float4*)(Wf + 256 * 128 + c);
    float4 wse = *(const float4*)(Ws + 256 * 128 + c);
    float4 bfv = *(const float4*)(bf + c);
    float4 bsv = *(const float4*)(bs + c);

    float4 m;
    m.x = sigm_f(pif.x + pjf.x + ev * wfe.x + bfv.x) * sp_f(pis.x + pjs.x + ev * wse.x + bsv.x);
    m.y = sigm_f(pif.y + pjf.y + ev * wfe.y + bfv.y) * sp_f(pis.y + pjs.y + ev * wse.y + bsv.y);
    m.z = sigm_f(pif.z + pjf.z + ev * wfe.z + bfv.z) * sp_f(pis.z + pjs.z + ev * wse.z + bsv.z);
    m.w = sigm_f(pif.w + pjf.w + ev * wfe.w + bfv.w) * sp_f(pis.w + pjs.w + ev * wse.w + bsv.w);

    float* dstp = g_aggr + (size_t)dst * CC + c;
    asm volatile("red.global.add.v4.f32 [%0], {%1, %2, %3, %4};"
                 :: "l"(dstp), "f"(m.x), "f"(m.y), "f"(m.z), "f"(m.w)
                 : "memory");
}

// Per-channel sum / sumsq over g_aggr
__global__ void bn_stats() {
    int ch = threadIdx.x & 127;
    int r = blockIdx.x * 2 + (threadIdx.x >> 7);
    float s = 0.f, s2 = 0.f;
    for (; r < NN; r += gridDim.x * 2) {
        float v = g_aggr[(size_t)r * CC + ch];
        s += v;
        s2 += v * v;
    }
    atomicAdd(g_stats + ch, s);
    atomicAdd(g_stats + CC + ch, s2);
}

// out_final = 2*out + batchnorm(aggr)
__global__ void finalize(const float* __restrict__ gamma, const float* __restrict__ beta,
                         float* __restrict__ out) {
    int i4 = blockIdx.x * blockDim.x + threadIdx.x;   // over N*32 float4s
    if (i4 >= NN * 32) return;
    int c = (i4 & 31) * 4;
    float4 a = *(const float4*)(g_aggr + (size_t)i4 * 4);
    float4 o = *(const float4*)(g_out + (size_t)i4 * 4);
    const float inv = 1.0f / NN;
    float4 r;
#pragma unroll
    for (int j = 0; j < 4; j++) {
        float sum = g_stats[c + j];
        float sq = g_stats[CC + c + j];
        float mean = sum * inv;
        float var = sq * inv - mean * mean;
        float scale = rsqrtf(var + 1e-5f) * gamma[c + j];
        float av = (&a.x)[j];
        float ov = (&o.x)[j];
        (&r.x)[j] = 2.0f * ov + (av - mean) * scale + beta[c + j];
    }
    *(float4*)(out + (size_t)i4 * 4) = r;
}

extern "C" void kernel_launch(void* const* d_in, const int* in_sizes, int n_in,
                              void* d_out, int out_size) {
    const float* h    = (const float*)d_in[0];
    const int*   ei   = (const int*)d_in[1];
    // d_in[2] = edge_weight (unused by reference)
    const float* ea   = (const float*)d_in[3];
    const float* W0   = (const float*)d_in[4];
    const float* b0   = (const float*)d_in[5];
    const float* Wsh  = (const float*)d_in[6];
    const float* bsh  = (const float*)d_in[7];
    const float* Wf   = (const float*)d_in[8];
    const float* bf   = (const float*)d_in[9];
    const float* Ws   = (const float*)d_in[10];
    const float* bs   = (const float*)d_in[11];
    const float* gamma = (const float*)d_in[12];
    const float* beta  = (const float*)d_in[13];
    float* out = (float*)d_out;

    float *p_out, *p_P, *p_Wcat;
    cudaGetSymbolAddress((void**)&p_out, g_out);
    cudaGetSymbolAddress((void**)&p_P, g_P);
    cudaGetSymbolAddress((void**)&p_Wcat, g_Wcat);

    zero_kernel<<<2048, 256>>>();
    prep_wcat<<<(KK * 512 + 255) / 256, 256>>>(Wf, Ws);

    // out = softplus(h @ W0 + b0)
    gemm64<1><<<dim3((NN + 63) / 64, CC / 64), 256>>>(h, W0, b0, p_out, NN, CC);
    // P = out @ Wcat  (packed node-side linear parts)
    gemm64<0><<<dim3((NN + 63) / 64, 512 / 64), 256>>>(p_out, p_Wcat, nullptr, p_P, NN, 512);

    edge_gauss<<<(EE * 32 + 255) / 256, 256>>>(ea, Wsh, bsh);
    edge_msg<<<(EE * 32 + 255) / 256, 256>>>(ei, Wf, Ws, bf, bs);

    bn_stats<<<512, 256>>>();
    finalize<<<(NN * 32 + 255) / 256, 256>>>(gamma, beta, out);
}

// round 2
// speedup vs baseline: 1.0310x; 1.0310x over previous
#include <cuda_runtime.h>
#include <math.h>

#define NN 50000
#define EE 600000
#define CC 128
#define KK 128

// Scratch (static device globals; no runtime allocation allowed)
__device__ float g_out[(size_t)NN * CC];       // softplus(h@W0+b0)
__device__ float g_P[(size_t)NN * 512];        // [pi_f | pi_s | pj_f | pj_s] per node
__device__ float g_e[EE];                      // softplus(edge_attr@Wsh+bsh)
__device__ float g_aggr[(size_t)NN * CC];      // segment-sum accumulator
__device__ float g_stats[2 * CC];              // per-channel sum, sumsq
__device__ float g_Wcat[KK * 512];             // packed [Wf_i|Ws_i|Wf_j|Ws_j]

__device__ __forceinline__ float sp_f(float x) {
    return x > 20.0f ? x : log1pf(__expf(x));
}
__device__ __forceinline__ float sigm_f(float x) {
    return 1.0f / (1.0f + __expf(-x));
}

// Build Wcat[128][512]: cols 0-127 = Wf[:128] (x_i), 128-255 = Ws[:128],
// 256-383 = Wf[128:256] (x_j), 384-511 = Ws[128:256]
__global__ void prep_wcat(const float* __restrict__ Wf, const float* __restrict__ Ws) {
    int idx = blockIdx.x * blockDim.x + threadIdx.x;
    if (idx >= KK * 512) return;
    int k = idx >> 9;
    int c = idx & 511;
    float v;
    if (c < 128)      v = Wf[k * 128 + c];
    else if (c < 256) v = Ws[k * 128 + (c - 128)];
    else if (c < 384) v = Wf[(128 + k) * 128 + (c - 256)];
    else              v = Ws[(128 + k) * 128 + (c - 384)];
    g_Wcat[idx] = v;
}

// fp32 GEMM: C[M,Nc] = act(A[M,128] @ B[128,Nc] + bias)
// 128x128 tile, 256 threads, 8x8 microtile (split 4+4 rows/cols), BK=16.
template <int ACT>
__global__ void __launch_bounds__(256, 2)
gemm128(const float* __restrict__ A, const float* __restrict__ B,
        const float* __restrict__ bias, float* __restrict__ Co,
        int M, int Nc) {
    __shared__ float As[16][132];   // transposed: As[k][m]
    __shared__ float Bs[16][128];   // natural:    Bs[k][n]
    int tid = threadIdx.x;
    int tx = tid & 15, ty = tid >> 4;
    int row0 = blockIdx.x * 128, col0 = blockIdx.y * 128;
    float acc[8][8] = {};

    for (int kc = 0; kc < KK; kc += 16) {
        // Load A tile (transposed into smem)
#pragma unroll
        for (int l = 0; l < 2; l++) {
            int f = tid + l * 256;              // float4 id 0..511
            int m = f >> 2;                     // row in tile 0..127
            int kq = (f & 3) << 2;              // k offset 0,4,8,12
            int gr = row0 + m;
            float4 av = make_float4(0.f, 0.f, 0.f, 0.f);
            if (gr < M) av = *(const float4*)(A + (size_t)gr * KK + kc + kq);
            As[kq + 0][m] = av.x;
            As[kq + 1][m] = av.y;
            As[kq + 2][m] = av.z;
            As[kq + 3][m] = av.w;
        }
        // Load B tile
#pragma unroll
        for (int l = 0; l < 2; l++) {
            int f = tid + l * 256;
            int k = f >> 5;                     // 0..15
            int c4 = (f & 31) << 2;             // 0..124
            *(float4*)&Bs[k][c4] = *(const float4*)(B + (size_t)(kc + k) * Nc + col0 + c4);
        }
        __syncthreads();

#pragma unroll
        for (int k = 0; k < 16; k++) {
            float4 a0 = *(float4*)&As[k][ty * 4];
            float4 a1 = *(float4*)&As[k][64 + ty * 4];
            float4 b0 = *(float4*)&Bs[k][tx * 4];
            float4 b1 = *(float4*)&Bs[k][64 + tx * 4];
            float ar[8] = {a0.x, a0.y, a0.z, a0.w, a1.x, a1.y, a1.z, a1.w};
            float br[8] = {b0.x, b0.y, b0.z, b0.w, b1.x, b1.y, b1.z, b1.w};
#pragma unroll
            for (int i = 0; i < 8; i++)
#pragma unroll
                for (int j = 0; j < 8; j++)
                    acc[i][j] += ar[i] * br[j];
        }
        __syncthreads();
    }

    // Epilogue
#pragma unroll
    for (int i = 0; i < 8; i++) {
        int gr = row0 + (i < 4 ? ty * 4 + i : 64 + ty * 4 + (i - 4));
        if (gr >= M) continue;
#pragma unroll
        for (int half = 0; half < 2; half++) {
            int gc = col0 + half * 64 + tx * 4;
            float4 v;
            v.x = acc[i][half * 4 + 0];
            v.y = acc[i][half * 4 + 1];
            v.z = acc[i][half * 4 + 2];
            v.w = acc[i][half * 4 + 3];
            if (ACT) {
                v.x = sp_f(v.x + bias[gc + 0]);
                v.y = sp_f(v.y + bias[gc + 1]);
                v.z = sp_f(v.z + bias[gc + 2]);
                v.w = sp_f(v.w + bias[gc + 3]);
            }
            *(float4*)(Co + (size_t)gr * Nc + gc) = v;
        }
    }
}

// e = softplus(edge_attr @ Wsh + bsh): one warp per edge
__global__ void edge_gauss(const float* __restrict__ ea, const float* __restrict__ Wsh,
                           const float* __restrict__ bsh) {
    int t = blockIdx.x * blockDim.x + threadIdx.x;
    int e = t >> 5;
    if (e >= EE) return;
    int lane = t & 31;
    float4 a = *(const float4*)(ea + (size_t)e * 128 + lane * 4);
    float4 w = *(const float4*)(Wsh + lane * 4);
    float d = a.x * w.x + a.y * w.y + a.z * w.z + a.w * w.w;
#pragma unroll
    for (int o = 16; o; o >>= 1) d += __shfl_xor_sync(0xFFFFFFFFu, d, o);
    if (lane == 0) g_e[e] = sp_f(d + bsh[0]);
}

// One warp per edge: gate*core message, vectorized reduction into g_aggr[dst]
__global__ void edge_msg(const int* __restrict__ ei, const float* __restrict__ Wf,
                         const float* __restrict__ Ws, const float* __restrict__ bf,
                         const float* __restrict__ bs) {
    int t = blockIdx.x * blockDim.x + threadIdx.x;
    int e = t >> 5;
    if (e >= EE) return;
    int lane = t & 31;
    int src = __ldg(ei + e);
    int dst = __ldg(ei + EE + e);
    float ev = __ldg(g_e + e);
    int c = lane * 4;

    const float4* Pd = (const float4*)(g_P + (size_t)dst * 512);        // [pi_f|pi_s]
    const float4* Psrc = (const float4*)(g_P + (size_t)src * 512 + 256); // [pj_f|pj_s]
    float4 pif = Pd[lane];
    float4 pis = Pd[32 + lane];
    float4 pjf = Psrc[lane];
    float4 pjs = Psrc[32 + lane];

    float4 wfe = *(const float4*)(Wf + 256 * 128 + c);
    float4 wse = *(const float4*)(Ws + 256 * 128 + c);
    float4 bfv = *(const float4*)(bf + c);
    float4 bsv = *(const float4*)(bs + c);

    float4 m;
    m.x = sigm_f(pif.x + pjf.x + ev * wfe.x + bfv.x) * sp_f(pis.x + pjs.x + ev * wse.x + bsv.x);
    m.y = sigm_f(pif.y + pjf.y + ev * wfe.y + bfv.y) * sp_f(pis.y + pjs.y + ev * wse.y + bsv.y);
    m.z = sigm_f(pif.z + pjf.z + ev * wfe.z + bfv.z) * sp_f(pis.z + pjs.z + ev * wse.z + bsv.z);
    m.w = sigm_f(pif.w + pjf.w + ev * wfe.w + bfv.w) * sp_f(pis.w + pjs.w + ev * wse.w + bsv.w);

    float* dstp = g_aggr + (size_t)dst * CC + c;
    asm volatile("red.global.add.v4.f32 [%0], {%1, %2, %3, %4};"
                 :: "l"(dstp), "f"(m.x), "f"(m.y), "f"(m.z), "f"(m.w)
                 : "memory");
}

// Per-channel sum / sumsq over g_aggr
__global__ void bn_stats() {
    int ch = threadIdx.x & 127;
    int r = blockIdx.x * 2 + (threadIdx.x >> 7);
    float s = 0.f, s2 = 0.f;
    for (; r < NN; r += gridDim.x * 2) {
        float v = g_aggr[(size_t)r * CC + ch];
        s += v;
        s2 += v * v;
    }
    atomicAdd(g_stats + ch, s);
    atomicAdd(g_stats + CC + ch, s2);
}

// out_final = 2*out + batchnorm(aggr)
__global__ void finalize(const float* __restrict__ gamma, const float* __restrict__ beta,
                         float* __restrict__ out) {
    int i4 = blockIdx.x * blockDim.x + threadIdx.x;   // over N*32 float4s
    if (i4 >= NN * 32) return;
    int c = (i4 & 31) * 4;
    float4 a = *(const float4*)(g_aggr + (size_t)i4 * 4);
    float4 o = *(const float4*)(g_out + (size_t)i4 * 4);
    const float inv = 1.0f / NN;
    float4 r;
#pragma unroll
    for (int j = 0; j < 4; j++) {
        float sum = g_stats[c + j];
        float sq = g_stats[CC + c + j];
        float mean = sum * inv;
        float var = sq * inv - mean * mean;
        float scale = rsqrtf(var + 1e-5f) * gamma[c + j];
        float av = (&a.x)[j];
        float ov = (&o.x)[j];
        (&r.x)[j] = 2.0f * ov + (av - mean) * scale + beta[c + j];
    }
    *(float4*)(out + (size_t)i4 * 4) = r;
}

extern "C" void kernel_launch(void* const* d_in, const int* in_sizes, int n_in,
                              void* d_out, int out_size) {
    const float* h    = (const float*)d_in[0];
    const int*   ei   = (const int*)d_in[1];
    // d_in[2] = edge_weight (unused by reference)
    const float* ea   = (const float*)d_in[3];
    const float* W0   = (const float*)d_in[4];
    const float* b0   = (const float*)d_in[5];
    const float* Wsh  = (const float*)d_in[6];
    const float* bsh  = (const float*)d_in[7];
    const float* Wf   = (const float*)d_in[8];
    const float* bf   = (const float*)d_in[9];
    const float* Ws   = (const float*)d_in[10];
    const float* bs   = (const float*)d_in[11];
    const float* gamma = (const float*)d_in[12];
    const float* beta  = (const float*)d_in[13];
    float* out = (float*)d_out;

    float *p_out, *p_P, *p_Wcat, *p_aggr, *p_stats;
    cudaGetSymbolAddress((void**)&p_out, g_out);
    cudaGetSymbolAddress((void**)&p_P, g_P);
    cudaGetSymbolAddress((void**)&p_Wcat, g_Wcat);
    cudaGetSymbolAddress((void**)&p_aggr, g_aggr);
    cudaGetSymbolAddress((void**)&p_stats, g_stats);

    cudaMemsetAsync(p_aggr, 0, (size_t)NN * CC * sizeof(float));
    cudaMemsetAsync(p_stats, 0, 2 * CC * sizeof(float));
    prep_wcat<<<(KK * 512 + 255) / 256, 256>>>(Wf, Ws);

    // out = softplus(h @ W0 + b0)
    gemm128<1><<<dim3((NN + 127) / 128, CC / 128), 256>>>(h, W0, b0, p_out, NN, CC);
    // P = out @ Wcat  (packed node-side linear parts)
    gemm128<0><<<dim3((NN + 127) / 128, 512 / 128), 256>>>(p_out, p_Wcat, nullptr, p_P, NN, 512);

    edge_gauss<<<(EE * 32 + 255) / 256, 256>>>(ea, Wsh, bsh);
    edge_msg<<<(EE * 32 + 255) / 256, 256>>>(ei, Wf, Ws, bf, bs);

    bn_stats<<<512, 256>>>();
    finalize<<<(NN * 32 + 255) / 256, 256>>>(gamma, beta, out);
}

// round 3
// speedup vs baseline: 1.1105x; 1.0771x over previous
#include <cuda_runtime.h>
#include <math.h>

#define NN 50000
#define EE 600000
#define CC 128
#define KK 128
#define SCAN_BLOCKS ((NN + 255) / 256)   // 196

// Scratch (static device globals; no runtime allocation allowed)
__device__ float g_out[(size_t)NN * CC];       // softplus(h@W0+b0)
__device__ float g_P[(size_t)NN * 512];        // [pi_f | pi_s | pj_f | pj_s] per node
__device__ float g_e[EE];                      // softplus(edge_attr@Wsh+bsh)
__device__ float g_aggr[(size_t)NN * CC];      // segment-sum result
__device__ float g_stats[2 * CC];              // per-channel sum, sumsq
__device__ float g_Wcat[KK * 512];             // packed [Wf_i|Ws_i|Wf_j|Ws_j]
// CSR scratch
__device__ int   g_deg[NN];
__device__ int   g_roff[NN];
__device__ int   g_cursor[NN];
__device__ int   g_bsum[SCAN_BLOCKS];
__device__ int   g_boff[SCAN_BLOCKS];
__device__ int   g_esrc[EE];                   // src sorted by dst
__device__ float g_ee[EE];                     // e value sorted by dst

__device__ __forceinline__ float sp_f(float x) {
    return x > 20.0f ? x : log1pf(__expf(x));
}
__device__ __forceinline__ float sigm_f(float x) {
    return 1.0f / (1.0f + __expf(-x));
}

// ---------------- weight packing ----------------
__global__ void prep_wcat(const float* __restrict__ Wf, const float* __restrict__ Ws) {
    int idx = blockIdx.x * blockDim.x + threadIdx.x;
    if (idx >= KK * 512) return;
    int k = idx >> 9;
    int c = idx & 511;
    float v;
    if (c < 128)      v = Wf[k * 128 + c];
    else if (c < 256) v = Ws[k * 128 + (c - 128)];
    else if (c < 384) v = Wf[(128 + k) * 128 + (c - 256)];
    else              v = Ws[(128 + k) * 128 + (c - 384)];
    g_Wcat[idx] = v;
}

// ---------------- GEMM (fp32, 128x128 tile, 8x8 microtile) ----------------
template <int ACT>
__global__ void __launch_bounds__(256, 2)
gemm128(const float* __restrict__ A, const float* __restrict__ B,
        const float* __restrict__ bias, float* __restrict__ Co,
        int M, int Nc) {
    __shared__ float As[16][132];
    __shared__ float Bs[16][128];
    int tid = threadIdx.x;
    int tx = tid & 15, ty = tid >> 4;
    int row0 = blockIdx.x * 128, col0 = blockIdx.y * 128;
    float acc[8][8] = {};

    for (int kc = 0; kc < KK; kc += 16) {
#pragma unroll
        for (int l = 0; l < 2; l++) {
            int f = tid + l * 256;
            int m = f >> 2;
            int kq = (f & 3) << 2;
            int gr = row0 + m;
            float4 av = make_float4(0.f, 0.f, 0.f, 0.f);
            if (gr < M) av = *(const float4*)(A + (size_t)gr * KK + kc + kq);
            As[kq + 0][m] = av.x;
            As[kq + 1][m] = av.y;
            As[kq + 2][m] = av.z;
            As[kq + 3][m] = av.w;
        }
#pragma unroll
        for (int l = 0; l < 2; l++) {
            int f = tid + l * 256;
            int k = f >> 5;
            int c4 = (f & 31) << 2;
            *(float4*)&Bs[k][c4] = *(const float4*)(B + (size_t)(kc + k) * Nc + col0 + c4);
        }
        __syncthreads();

#pragma unroll
        for (int k = 0; k < 16; k++) {
            float4 a0 = *(float4*)&As[k][ty * 4];
            float4 a1 = *(float4*)&As[k][64 + ty * 4];
            float4 b0 = *(float4*)&Bs[k][tx * 4];
            float4 b1 = *(float4*)&Bs[k][64 + tx * 4];
            float ar[8] = {a0.x, a0.y, a0.z, a0.w, a1.x, a1.y, a1.z, a1.w};
            float br[8] = {b0.x, b0.y, b0.z, b0.w, b1.x, b1.y, b1.z, b1.w};
#pragma unroll
            for (int i = 0; i < 8; i++)
#pragma unroll
                for (int j = 0; j < 8; j++)
                    acc[i][j] += ar[i] * br[j];
        }
        __syncthreads();
    }

#pragma unroll
    for (int i = 0; i < 8; i++) {
        int gr = row0 + (i < 4 ? ty * 4 + i : 64 + ty * 4 + (i - 4));
        if (gr >= M) continue;
#pragma unroll
        for (int half = 0; half < 2; half++) {
            int gc = col0 + half * 64 + tx * 4;
            float4 v;
            v.x = acc[i][half * 4 + 0];
            v.y = acc[i][half * 4 + 1];
            v.z = acc[i][half * 4 + 2];
            v.w = acc[i][half * 4 + 3];
            if (ACT) {
                v.x = sp_f(v.x + bias[gc + 0]);
                v.y = sp_f(v.y + bias[gc + 1]);
                v.z = sp_f(v.z + bias[gc + 2]);
                v.w = sp_f(v.w + bias[gc + 3]);
            }
            *(float4*)(Co + (size_t)gr * Nc + gc) = v;
        }
    }
}

// ---------------- e = softplus(edge_attr @ Wsh + bsh) ----------------
// Half-warp per edge: lane l owns floats [l*4] and [64+l*4] -> 2 independent
// perfectly-coalesced float4 loads (MLP=2), 4-step half-warp shfl reduce.
__global__ void edge_gauss(const float* __restrict__ ea, const float* __restrict__ Wsh,
                           const float* __restrict__ bsh) {
    int t = blockIdx.x * blockDim.x + threadIdx.x;
    int e = t >> 4;
    if (e >= EE) return;
    int l = t & 15;
    const float* base = ea + (size_t)e * 128;
    float4 a0 = *(const float4*)(base + l * 4);
    float4 a1 = *(const float4*)(base + 64 + l * 4);
    float4 w0 = *(const float4*)(Wsh + l * 4);
    float4 w1 = *(const float4*)(Wsh + 64 + l * 4);
    float d = a0.x * w0.x + a0.y * w0.y + a0.z * w0.z + a0.w * w0.w
            + a1.x * w1.x + a1.y * w1.y + a1.z * w1.z + a1.w * w1.w;
#pragma unroll
    for (int o = 8; o; o >>= 1) d += __shfl_xor_sync(0xFFFFFFFFu, d, o);
    if (l == 0) g_e[e] = sp_f(d + bsh[0]);
}

// ---------------- CSR build ----------------
__global__ void hist(const int* __restrict__ ei) {
    int e = blockIdx.x * blockDim.x + threadIdx.x;
    if (e < EE) atomicAdd(&g_deg[ei[EE + e]], 1);
}

__global__ void scan_local() {
    __shared__ int s[256];
    int tid = threadIdx.x;
    int i = blockIdx.x * 256 + tid;
    int v = (i < NN) ? g_deg[i] : 0;
    s[tid] = v;
    __syncthreads();
#pragma unroll
    for (int off = 1; off < 256; off <<= 1) {
        int t = (tid >= off) ? s[tid - off] : 0;
        __syncthreads();
        s[tid] += t;
        __syncthreads();
    }
    if (i < NN) g_roff[i] = s[tid] - v;     // exclusive
    if (tid == 255) g_bsum[blockIdx.x] = s[255];
}

__global__ void scan_bsums() {
    __shared__ int s[256];
    int tid = threadIdx.x;
    int v = (tid < SCAN_BLOCKS) ? g_bsum[tid] : 0;
    s[tid] = v;
    __syncthreads();
#pragma unroll
    for (int off = 1; off < 256; off <<= 1) {
        int t = (tid >= off) ? s[tid - off] : 0;
        __syncthreads();
        s[tid] += t;
        __syncthreads();
    }
    if (tid < SCAN_BLOCKS) g_boff[tid] = s[tid] - v;   // exclusive
}

__global__ void scan_add() {
    int i = blockIdx.x * 256 + threadIdx.x;
    if (i < NN) {
        int r = g_roff[i] + g_boff[blockIdx.x];
        g_roff[i] = r;
        g_cursor[i] = r;
    }
}

__global__ void scatter(const int* __restrict__ ei) {
    int e = blockIdx.x * blockDim.x + threadIdx.x;
    if (e >= EE) return;
    int src = ei[e];
    int dst = ei[EE + e];
    int pos = atomicAdd(&g_cursor[dst], 1);
    g_esrc[pos] = src;
    g_ee[pos] = g_e[e];
}

// ---------------- CSR edge messages + fused BN stats ----------------
// One warp per dst node (strided). pi parts loaded once per node; plain
// stores to g_aggr (no atomics); per-block shared-mem stats then red.global.
__global__ void __launch_bounds__(256)
edge_msg_csr(const float* __restrict__ Wf, const float* __restrict__ Ws,
             const float* __restrict__ bf, const float* __restrict__ bs,
             int nwarps) {
    __shared__ float s_stats[2 * CC];
    int tid = threadIdx.x;
    int lane = tid & 31;
    int c = lane * 4;
    s_stats[tid] = 0.0f;
    __syncthreads();

    float4 wfe = *(const float4*)(Wf + 256 * 128 + c);
    float4 wse = *(const float4*)(Ws + 256 * 128 + c);
    float4 bfv = *(const float4*)(bf + c);
    float4 bsv = *(const float4*)(bs + c);

    float lsum[4] = {}, lsq[4] = {};

    int gw = blockIdx.x * 8 + (tid >> 5);
    for (int i = gw; i < NN; i += nwarps) {
        const float4* Pi = (const float4*)(g_P + (size_t)i * 512);
        float4 pif = Pi[lane];
        float4 pis = Pi[32 + lane];
        int k = g_roff[i];
        int end = k + g_deg[i];
        float4 acc = make_float4(0.f, 0.f, 0.f, 0.f);

        int src = 0; float ev = 0.f;
        if (k < end) { src = g_esrc[k]; ev = g_ee[k]; }
        while (k < end) {
            const float4* Pj = (const float4*)(g_P + (size_t)src * 512 + 256);
            float4 pjf = Pj[lane];
            float4 pjs = Pj[32 + lane];
            k++;
            int nsrc = 0; float nev = 0.f;
            if (k < end) { nsrc = g_esrc[k]; nev = g_ee[k]; }
            acc.x += sigm_f(pif.x + pjf.x + ev * wfe.x + bfv.x) * sp_f(pis.x + pjs.x + ev * wse.x + bsv.x);
            acc.y += sigm_f(pif.y + pjf.y + ev * wfe.y + bfv.y) * sp_f(pis.y + pjs.y + ev * wse.y + bsv.y);
            acc.z += sigm_f(pif.z + pjf.z + ev * wfe.z + bfv.z) * sp_f(pis.z + pjs.z + ev * wse.z + bsv.z);
            acc.w += sigm_f(pif.w + pjf.w + ev * wfe.w + bfv.w) * sp_f(pis.w + pjs.w + ev * wse.w + bsv.w);
            src = nsrc; ev = nev;
        }
        *(float4*)(g_aggr + (size_t)i * CC + c) = acc;
        lsum[0] += acc.x; lsum[1] += acc.y; lsum[2] += acc.z; lsum[3] += acc.w;
        lsq[0] += acc.x * acc.x; lsq[1] += acc.y * acc.y; lsq[2] += acc.z * acc.z; lsq[3] += acc.w * acc.w;
    }

#pragma unroll
    for (int j = 0; j < 4; j++) {
        atomicAdd(&s_stats[c + j], lsum[j]);
        atomicAdd(&s_stats[CC + c + j], lsq[j]);
    }
    __syncthreads();
    if (tid < 64) {
        float4 v = *(float4*)&s_stats[tid * 4];
        float* dstp = g_stats + tid * 4;
        asm volatile("red.global.add.v4.f32 [%0], {%1, %2, %3, %4};"
                     :: "l"(dstp), "f"(v.x), "f"(v.y), "f"(v.z), "f"(v.w)
                     : "memory");
    }
}

// ---------------- out_final = 2*out + batchnorm(aggr) ----------------
__global__ void finalize(const float* __restrict__ gamma, const float* __restrict__ beta,
                         float* __restrict__ out) {
    int i4 = blockIdx.x * blockDim.x + threadIdx.x;
    if (i4 >= NN * 32) return;
    int c = (i4 & 31) * 4;
    float4 a = *(const float4*)(g_aggr + (size_t)i4 * 4);
    float4 o = *(const float4*)(g_out + (size_t)i4 * 4);
    const float inv = 1.0f / NN;
    float4 r;
#pragma unroll
    for (int j = 0; j < 4; j++) {
        float sum = g_stats[c + j];
        float sq = g_stats[CC + c + j];
        float mean = sum * inv;
        float var = sq * inv - mean * mean;
        float scale = rsqrtf(var + 1e-5f) * gamma[c + j];
        float av = (&a.x)[j];
        float ov = (&o.x)[j];
        (&r.x)[j] = 2.0f * ov + (av - mean) * scale + beta[c + j];
    }
    *(float4*)(out + (size_t)i4 * 4) = r;
}

extern "C" void kernel_launch(void* const* d_in, const int* in_sizes, int n_in,
                              void* d_out, int out_size) {
    const float* h    = (const float*)d_in[0];
    const int*   ei   = (const int*)d_in[1];
    // d_in[2] = edge_weight (unused by reference)
    const float* ea   = (const float*)d_in[3];
    const float* W0   = (const float*)d_in[4];
    const float* b0   = (const float*)d_in[5];
    const float* Wsh  = (const float*)d_in[6];
    const float* bsh  = (const float*)d_in[7];
    const float* Wf   = (const float*)d_in[8];
    const float* bf   = (const float*)d_in[9];
    const float* Ws   = (const float*)d_in[10];
    const float* bs   = (const float*)d_in[11];
    const float* gamma = (const float*)d_in[12];
    const float* beta  = (const float*)d_in[13];
    float* out = (float*)d_out;

    float *p_out, *p_P, *p_Wcat, *p_stats;
    int *p_deg;
    cudaGetSymbolAddress((void**)&p_out, g_out);
    cudaGetSymbolAddress((void**)&p_P, g_P);
    cudaGetSymbolAddress((void**)&p_Wcat, g_Wcat);
    cudaGetSymbolAddress((void**)&p_stats, g_stats);
    cudaGetSymbolAddress((void**)&p_deg, g_deg);

    cudaMemsetAsync(p_stats, 0, 2 * CC * sizeof(float));
    cudaMemsetAsync(p_deg, 0, NN * sizeof(int));
    prep_wcat<<<(KK * 512 + 255) / 256, 256>>>(Wf, Ws);

    // CSR build (overlaps conceptually; stream-serial is fine)
    hist<<<(EE + 255) / 256, 256>>>(ei);
    scan_local<<<SCAN_BLOCKS, 256>>>();
    scan_bsums<<<1, 256>>>();
    scan_add<<<SCAN_BLOCKS, 256>>>();

    // out = softplus(h @ W0 + b0)
    gemm128<1><<<dim3((NN + 127) / 128, CC / 128), 256>>>(h, W0, b0, p_out, NN, CC);
    // P = out @ Wcat
    gemm128<0><<<dim3((NN + 127) / 128, 512 / 128), 256>>>(p_out, p_Wcat, nullptr, p_P, NN, 512);

    edge_gauss<<<(EE * 16 + 255) / 256, 256>>>(ea, Wsh, bsh);
    scatter<<<(EE + 255) / 256, 256>>>(ei);

    const int blocks = 1024;
    edge_msg_csr<<<blocks, 256>>>(Wf, Ws, bf, bs, blocks * 8);

    finalize<<<(NN * 32 + 255) / 256, 256>>>(gamma, beta, out);
}